// round 14
// baseline (speedup 1.0000x reference)
#include <cuda_runtime.h>
#include <cuda_fp16.h>
#include <math.h>

#define LEN 5440
#define NBATCH 2
#define MROWS (NBATCH*LEN)   /* 10880 */
#define DM 256
#define NH 8
#define DFFN 1024
#define NLAYERS 2
#define NQ 384

// gemmk tile: 128 x 128, K-chunk 64, 3-stage
#define TM 128
#define TN 128
#define KC 64
#define NSTAGE 3
#define ABYTES 16384
#define BBYTES 16384
#define SMEMG (NSTAGE*(ABYTES+BBYTES))   /* 98304 */

// gemmln tile: 32 x 256, 2-stage
#define LABYTES (32*128)     /* 4096 */
#define LBBYTES (256*128)    /* 32768 */
#define SMEML (2*(LABYTES+LBBYTES))   /* 73728 */

// gemmln64 tile: 64 x 256, 2-stage
#define MABYTES (64*128)     /* 8192 */
#define SMEM64 (2*(MABYTES+LBBYTES))  /* 81920 */

// preamble block ranges
#define NCVT (NLAYERS*737)         /* 1474 */
#define NINIT ((MROWS*DM+255)/256) /* 10880 */
#define NREF  ((MROWS+255)/256)    /* 43 */

__constant__ int c_HW[4] = {64, 32, 16, 8};
__constant__ int c_S[4]  = {0, 4096, 5120, 5376};

// ---------------- scratch ----------------
__device__ __align__(16) float  g_x[MROWS * DM];
__device__ __align__(16) __half g_xh[MROWS * DM];
__device__ __align__(16) __half g_qh[MROWS * DM];
__device__ __align__(16) __half g_valh[MROWS * DM];
__device__ __align__(16) float  g_offaw[MROWS * NQ];
__device__ __align__(16) __half g_attnh[MROWS * DM];
__device__ __align__(16) __half g_ffnh[MROWS * DFFN];
__device__ __align__(16) float  g_ref[MROWS * 8];
__device__ __align__(16) __half g_wvh[NLAYERS * DM * DM];
__device__ __align__(16) __half g_wqh[NLAYERS * NQ * DM];
__device__ __align__(16) __half g_woh[NLAYERS * DM * DM];
__device__ __align__(16) __half g_wl1h[NLAYERS * DM * DFFN];
__device__ __align__(16) __half g_wl2h[NLAYERS * DFFN * DM];
__device__ __align__(16) float  g_bq[NLAYERS * NQ];

// ---------------- helpers ----------------
__device__ __forceinline__ void cpa16(unsigned saddr, const void* g) {
    asm volatile("cp.async.cg.shared.global [%0], [%1], 16;" :: "r"(saddr), "l"(g));
}
__device__ __forceinline__ void ldsm4(unsigned& r0, unsigned& r1, unsigned& r2, unsigned& r3,
                                      unsigned addr) {
    asm volatile("ldmatrix.sync.aligned.m8n8.x4.shared.b16 {%0,%1,%2,%3}, [%4];"
                 : "=r"(r0), "=r"(r1), "=r"(r2), "=r"(r3) : "r"(addr));
}
#define MMA16816(C, A, B0, B1) \
    asm volatile("mma.sync.aligned.m16n8k16.row.col.f32.f16.f16.f32 " \
                 "{%0,%1,%2,%3}, {%4,%5,%6,%7}, {%8,%9}, {%0,%1,%2,%3};\n" \
                 : "+f"((C)[0]), "+f"((C)[1]), "+f"((C)[2]), "+f"((C)[3]) \
                 : "r"((A)[0]), "r"((A)[1]), "r"((A)[2]), "r"((A)[3]), "r"(B0), "r"(B1))

// ---------------- merged preamble: weight cvt+transpose | init | refpts ----------------
__global__ void pre_kernel(
    const float* __restrict__ Wv, const float* __restrict__ Woff, const float* __restrict__ Wa,
    const float* __restrict__ Wo, const float* __restrict__ Wl1, const float* __restrict__ Wl2,
    const float* __restrict__ boff, const float* __restrict__ ba,
    __half* __restrict__ wvh, __half* __restrict__ wqh, __half* __restrict__ woh,
    __half* __restrict__ wl1h, __half* __restrict__ wl2h, float* __restrict__ bq,
    const float* __restrict__ src, const float* __restrict__ pos,
    float* __restrict__ x, __half* __restrict__ xh, __half* __restrict__ qh,
    const float* __restrict__ vr, float* __restrict__ ref)
{
    __shared__ float tile[32][33];
    int b = blockIdx.x;
    int tid = threadIdx.x;

    if (b >= NCVT + NINIT) {                 // ---- refpts ----
        int idx = (b - NCVT - NINIT) * 256 + tid;
        if (idx >= MROWS) return;
        int n = idx / LEN, t = idx % LEN;
        int lvl = 3;
        if (t < 4096) lvl = 0; else if (t < 5120) lvl = 1; else if (t < 5376) lvl = 2;
        int s = c_S[lvl], hw = c_HW[lvl];
        int local = t - s;
        int i = local / hw, j = local % hw;
        float ry = (i + 0.5f) / (vr[(n * 4 + lvl) * 2 + 1] * (float)hw);
        float rx = (j + 0.5f) / (vr[(n * 4 + lvl) * 2 + 0] * (float)hw);
#pragma unroll
        for (int l2 = 0; l2 < 4; l2++) {
            ref[idx * 8 + l2 * 2 + 0] = rx * vr[(n * 4 + l2) * 2 + 0];
            ref[idx * 8 + l2 * 2 + 1] = ry * vr[(n * 4 + l2) * 2 + 1];
        }
        return;
    }
    if (b >= NCVT) {                          // ---- init ----
        int i = (b - NCVT) * 256 + tid;
        float s = src[i];
        x[i] = s;
        xh[i] = __float2half_rn(s);
        qh[i] = __float2half_rn(s + pos[i]);
        return;
    }
    // ---- weight convert + transpose ----
    int l = b / 737, r = b % 737;
    int tx = tid & 31, ty = tid >> 5;
    if (r == 736) {
        for (int i = tid; i < NQ; i += 256)
            bq[l * NQ + i] = (i < 256) ? boff[l * 256 + i] : ba[l * 128 + i - 256];
        return;
    }
    const float* srcw; __half* dst; int K, N, t, rowOff = 0;
    if (r < 64)       { srcw = Wv   + (size_t)l * 256 * 256;  dst = wvh  + (size_t)l * 256 * 256;  K = 256;  N = 256;  t = r; }
    else if (r < 128) { srcw = Woff + (size_t)l * 256 * 256;  dst = wqh  + (size_t)l * NQ * 256;   K = 256;  N = 256;  t = r - 64; }
    else if (r < 160) { srcw = Wa   + (size_t)l * 256 * 128;  dst = wqh  + (size_t)l * NQ * 256;   K = 256;  N = 128;  t = r - 128; rowOff = 256; }
    else if (r < 224) { srcw = Wo   + (size_t)l * 256 * 256;  dst = woh  + (size_t)l * 256 * 256;  K = 256;  N = 256;  t = r - 160; }
    else if (r < 480) { srcw = Wl1  + (size_t)l * 256 * 1024; dst = wl1h + (size_t)l * 256 * 1024; K = 256;  N = 1024; t = r - 224; }
    else              { srcw = Wl2  + (size_t)l * 1024 * 256; dst = wl2h + (size_t)l * 1024 * 256; K = 1024; N = 256;  t = r - 480; }
    int tn = t % (N / 32), tk = t / (N / 32);
    int k0 = tk * 32, n0 = tn * 32;
#pragma unroll
    for (int i = ty; i < 32; i += 8)
        tile[i][tx] = srcw[(size_t)(k0 + i) * N + n0 + tx];
    __syncthreads();
#pragma unroll
    for (int i = ty; i < 32; i += 8)
        dst[(size_t)(rowOff + n0 + i) * K + k0 + tx] = __float2half_rn(tile[tx][i]);
}

// ---------------- gemmk: 128x128 tile, 3-stage ----------------
struct GP {
    const __half* A; const __half* W; const float* bias; void* C;
    int K; int Nc; int mode;
};

__global__ void __launch_bounds__(256, 2) gemmk(GP p0, GP p1, int split)
{
    extern __shared__ char smc[];
    unsigned sbase = (unsigned)__cvta_generic_to_shared(smc);
    unsigned sA = sbase;
    unsigned sB = sbase + NSTAGE * ABYTES;

    GP p; int bx = blockIdx.x;
    if (bx < split) p = p0; else { p = p1; bx -= split; }

    int tid  = threadIdx.x;
    int lane = tid & 31;
    int warp = tid >> 5;
    int wm = warp >> 2, wn = warp & 3;
    int gid = lane >> 2, tq = lane & 3;
    int l7 = lane & 7;

    int rowBase = blockIdx.y * TM;
    int colBase = bx * TN;
    int K = p.K;

    int pr = tid >> 3;
    int pc = tid & 7;
    const __half* Ag = p.A + (size_t)(rowBase + pr) * K + pc * 8;
    const __half* Wg = p.W + (size_t)(colBase + pr) * K + pc * 8;
    unsigned swp = (unsigned)((pc ^ (pr & 7)) << 4);
    unsigned adst0 = sA + (unsigned)(pr * 128) + swp;
    unsigned bdst0 = sB + (unsigned)(pr * 128) + swp;

    auto issue = [&](int s, int k0) {
        unsigned ad = adst0 + (unsigned)(s * ABYTES);
        unsigned bd = bdst0 + (unsigned)(s * BBYTES);
#pragma unroll
        for (int i = 0; i < 4; i++) {
            cpa16(ad + (unsigned)(i * 4096), Ag + (size_t)(32 * i) * K + k0);
            cpa16(bd + (unsigned)(i * 4096), Wg + (size_t)(32 * i) * K + k0);
        }
        asm volatile("cp.async.commit_group;");
    };

    int rlocA = lane & 15, hvA = lane >> 4;
    unsigned rowA[4];
#pragma unroll
    for (int mt = 0; mt < 4; mt++)
        rowA[mt] = sA + (unsigned)((wm * 64 + mt * 16 + rlocA) * 128);
    int nrow = ((lane >> 4) & 1) * 8 + l7;
    int hvB = (lane >> 3) & 1;
    unsigned rowB[2];
#pragma unroll
    for (int pp = 0; pp < 2; pp++)
        rowB[pp] = sB + (unsigned)((wn * 32 + pp * 16 + nrow) * 128);

    float c[4][4][4];
#pragma unroll
    for (int i = 0; i < 4; i++)
#pragma unroll
        for (int j = 0; j < 4; j++)
#pragma unroll
            for (int r = 0; r < 4; r++) c[i][j][r] = 0.f;

    int T = K / KC;
    issue(0, 0);
    issue(1, KC);

#pragma unroll 1
    for (int t = 0; t < T; t++) {
        asm volatile("cp.async.wait_group 1;");
        __syncthreads();
        if (t + 2 < T) issue((t + 2) % NSTAGE, (t + 2) * KC);
        else asm volatile("cp.async.commit_group;");

        unsigned aoff = (unsigned)((t % NSTAGE) * ABYTES);
        unsigned boff = (unsigned)((t % NSTAGE) * BBYTES);

#pragma unroll
        for (int ks = 0; ks < 4; ks++) {
            unsigned swcA = (unsigned)(((2 * ks + hvA) ^ l7) << 4);
            unsigned swcB = (unsigned)(((2 * ks + hvB) ^ l7) << 4);
            unsigned aa[4][4], bb[2][4];
#pragma unroll
            for (int mt = 0; mt < 4; mt++)
                ldsm4(aa[mt][0], aa[mt][1], aa[mt][2], aa[mt][3], rowA[mt] + aoff + swcA);
#pragma unroll
            for (int pp = 0; pp < 2; pp++)
                ldsm4(bb[pp][0], bb[pp][1], bb[pp][2], bb[pp][3], rowB[pp] + boff + swcB);
#pragma unroll
            for (int pp = 0; pp < 2; pp++)
#pragma unroll
                for (int q = 0; q < 2; q++) {
                    int nt = 2 * pp + q;
#pragma unroll
                    for (int mt = 0; mt < 4; mt++)
                        MMA16816(c[mt][nt], aa[mt], bb[pp][2 * q], bb[pp][2 * q + 1]);
                }
        }
        __syncthreads();
    }

    int Nc = p.Nc, mode = p.mode;
#pragma unroll
    for (int mt = 0; mt < 4; mt++) {
#pragma unroll
        for (int nt = 0; nt < 4; nt++) {
            int r0 = rowBase + wm * 64 + mt * 16 + gid;
            int cc = colBase + wn * 32 + nt * 8 + tq * 2;
            float b0v = p.bias[cc], b1v = p.bias[cc + 1];
            float v0 = c[mt][nt][0] + b0v, v1 = c[mt][nt][1] + b1v;
            float v2 = c[mt][nt][2] + b0v, v3 = c[mt][nt][3] + b1v;
            if (mode == 0) {
                float* C = (float*)p.C;
                *(float2*)(C + (size_t)r0 * Nc + cc)       = make_float2(v0, v1);
                *(float2*)(C + (size_t)(r0 + 8) * Nc + cc) = make_float2(v2, v3);
            } else {
                if (mode == 2) {
                    v0 = fmaxf(v0, 0.f); v1 = fmaxf(v1, 0.f);
                    v2 = fmaxf(v2, 0.f); v3 = fmaxf(v3, 0.f);
                }
                __half* C = (__half*)p.C;
                *(__half2*)(C + (size_t)r0 * Nc + cc)       = __floats2half2_rn(v0, v1);
                *(__half2*)(C + (size_t)(r0 + 8) * Nc + cc) = __floats2half2_rn(v2, v3);
            }
        }
    }
}

// ---------------- gemmln: 32x256 tile, fused bias+residual+LayerNorm (Wo) ----------------
// mode: 3 = write x + xh ; 4 = write x + xh + qh ; 5 = final, write out only.
struct GLP {
    const __half* A; const __half* W; const float* bias;
    const float* g; const float* be; const float* pos;
    const float* xres; float* xout; __half* xh; __half* qh;
    int K; int mode;
};

__global__ void __launch_bounds__(256, 3) gemmln(GLP p)
{
    extern __shared__ char smc[];
    unsigned sbase = (unsigned)__cvta_generic_to_shared(smc);
    unsigned sA = sbase;
    unsigned sB = sbase + 2 * LABYTES;

    int tid  = threadIdx.x;
    int lane = tid & 31;
    int wn   = tid >> 5;
    int gid = lane >> 2, tq = lane & 3;
    int l7 = lane & 7;

    int rowBase = blockIdx.y * 32;
    int K = p.K;

    int pr = tid >> 3;
    int pc = tid & 7;
    const __half* Ag = p.A + (size_t)(rowBase + pr) * K + pc * 8;
    const __half* Wg = p.W + (size_t)pr * K + pc * 8;
    unsigned swp = (unsigned)((pc ^ (pr & 7)) << 4);
    unsigned adst0 = sA + (unsigned)(pr * 128) + swp;
    unsigned bdst0 = sB + (unsigned)(pr * 128) + swp;

    auto issue = [&](int s, int k0) {
        cpa16(adst0 + (unsigned)(s * LABYTES), Ag + k0);
        unsigned bd = bdst0 + (unsigned)(s * LBBYTES);
#pragma unroll
        for (int i = 0; i < 8; i++)
            cpa16(bd + (unsigned)(i * 4096), Wg + (size_t)(32 * i) * K + k0);
        asm volatile("cp.async.commit_group;");
    };

    int rlocA = lane & 15, hvA = lane >> 4;
    unsigned rowA[2];
#pragma unroll
    for (int mt = 0; mt < 2; mt++)
        rowA[mt] = sA + (unsigned)((mt * 16 + rlocA) * 128);
    int nrow = ((lane >> 4) & 1) * 8 + l7;
    int hvB = (lane >> 3) & 1;
    unsigned rowB[2];
#pragma unroll
    for (int pp = 0; pp < 2; pp++)
        rowB[pp] = sB + (unsigned)((wn * 32 + pp * 16 + nrow) * 128);

    float c[2][4][4];
#pragma unroll
    for (int i = 0; i < 2; i++)
#pragma unroll
        for (int j = 0; j < 4; j++)
#pragma unroll
            for (int r = 0; r < 4; r++) c[i][j][r] = 0.f;

    int T = K / KC;
    issue(0, 0);

#pragma unroll 1
    for (int t = 0; t < T; t++) {
        asm volatile("cp.async.wait_group 0;");
        __syncthreads();
        if (t + 1 < T) issue((t + 1) & 1, (t + 1) * KC);

        unsigned aoff = (unsigned)((t & 1) * LABYTES);
        unsigned boff = (unsigned)((t & 1) * LBBYTES);

#pragma unroll
        for (int ks = 0; ks < 4; ks++) {
            unsigned swcA = (unsigned)(((2 * ks + hvA) ^ l7) << 4);
            unsigned swcB = (unsigned)(((2 * ks + hvB) ^ l7) << 4);
            unsigned aa[2][4], bb[2][4];
#pragma unroll
            for (int mt = 0; mt < 2; mt++)
                ldsm4(aa[mt][0], aa[mt][1], aa[mt][2], aa[mt][3], rowA[mt] + aoff + swcA);
#pragma unroll
            for (int pp = 0; pp < 2; pp++)
                ldsm4(bb[pp][0], bb[pp][1], bb[pp][2], bb[pp][3], rowB[pp] + boff + swcB);
#pragma unroll
            for (int pp = 0; pp < 2; pp++)
#pragma unroll
                for (int q = 0; q < 2; q++) {
                    int nt = 2 * pp + q;
#pragma unroll
                    for (int mt = 0; mt < 2; mt++)
                        MMA16816(c[mt][nt], aa[mt], bb[pp][2 * q], bb[pp][2 * q + 1]);
                }
        }
        __syncthreads();
    }

    // ---- fused epilogue ----
    float* red = (float*)smc;
    if (tid < 64) red[tid] = 0.f;
    __syncthreads();

#pragma unroll
    for (int mt = 0; mt < 2; mt++) {
        int rl0 = mt * 16 + gid;
        int r0 = rowBase + rl0;
        float s0 = 0.f, ss0 = 0.f, s1 = 0.f, ss1 = 0.f;
#pragma unroll
        for (int nt = 0; nt < 4; nt++) {
            int cc = wn * 32 + nt * 8 + tq * 2;
            float b0 = __ldg(p.bias + cc), b1 = __ldg(p.bias + cc + 1);
            float2 x0 = *(const float2*)(p.xres + (size_t)r0 * DM + cc);
            float2 x1 = *(const float2*)(p.xres + (size_t)(r0 + 8) * DM + cc);
            float v0 = c[mt][nt][0] + b0 + x0.x;
            float v1 = c[mt][nt][1] + b1 + x0.y;
            float v2 = c[mt][nt][2] + b0 + x1.x;
            float v3 = c[mt][nt][3] + b1 + x1.y;
            c[mt][nt][0] = v0; c[mt][nt][1] = v1; c[mt][nt][2] = v2; c[mt][nt][3] = v3;
            s0 += v0 + v1; ss0 += v0 * v0 + v1 * v1;
            s1 += v2 + v3; ss1 += v2 * v2 + v3 * v3;
        }
#pragma unroll
        for (int o = 1; o <= 2; o <<= 1) {
            s0  += __shfl_xor_sync(0xffffffffu, s0, o);
            ss0 += __shfl_xor_sync(0xffffffffu, ss0, o);
            s1  += __shfl_xor_sync(0xffffffffu, s1, o);
            ss1 += __shfl_xor_sync(0xffffffffu, ss1, o);
        }
        if (tq == 0) {
            atomicAdd(&red[2 * rl0], s0);
            atomicAdd(&red[2 * rl0 + 1], ss0);
            atomicAdd(&red[2 * (rl0 + 8)], s1);
            atomicAdd(&red[2 * (rl0 + 8) + 1], ss1);
        }
    }
    __syncthreads();

    int mode = p.mode;
#pragma unroll
    for (int mt = 0; mt < 2; mt++) {
        int rl0 = mt * 16 + gid;
        int r0 = rowBase + rl0;
        float mean0 = red[2 * rl0] * (1.0f / DM);
        float var0  = red[2 * rl0 + 1] * (1.0f / DM) - mean0 * mean0;
        float rstd0 = rsqrtf(var0 + 1e-5f);
        float mean1 = red[2 * (rl0 + 8)] * (1.0f / DM);
        float var1  = red[2 * (rl0 + 8) + 1] * (1.0f / DM) - mean1 * mean1;
        float rstd1 = rsqrtf(var1 + 1e-5f);
#pragma unroll
        for (int nt = 0; nt < 4; nt++) {
            int cc = wn * 32 + nt * 8 + tq * 2;
            float gg0 = __ldg(p.g + cc), gg1 = __ldg(p.g + cc + 1);
            float bb0 = __ldg(p.be + cc), bb1 = __ldg(p.be + cc + 1);
            float v0 = (c[mt][nt][0] - mean0) * rstd0 * gg0 + bb0;
            float v1 = (c[mt][nt][1] - mean0) * rstd0 * gg1 + bb1;
            float v2 = (c[mt][nt][2] - mean1) * rstd1 * gg0 + bb0;
            float v3 = (c[mt][nt][3] - mean1) * rstd1 * gg1 + bb1;
            size_t o0 = (size_t)r0 * DM + cc;
            size_t o1 = (size_t)(r0 + 8) * DM + cc;
            if (mode == 5) {
                *(float2*)(p.xout + o0) = make_float2(v0, v1);
                *(float2*)(p.xout + o1) = make_float2(v2, v3);
            } else {
                *(float2*)(p.xout + o0) = make_float2(v0, v1);
                *(float2*)(p.xout + o1) = make_float2(v2, v3);
                *(__half2*)(p.xh + o0) = __floats2half2_rn(v0, v1);
                *(__half2*)(p.xh + o1) = __floats2half2_rn(v2, v3);
                if (mode == 4) {
                    float2 p0 = *(const float2*)(p.pos + o0);
                    float2 p1 = *(const float2*)(p.pos + o1);
                    *(__half2*)(p.qh + o0) = __floats2half2_rn(v0 + p0.x, v1 + p0.y);
                    *(__half2*)(p.qh + o1) = __floats2half2_rn(v2 + p1.x, v3 + p1.y);
                }
            }
        }
    }
}

// ---------------- gemmln64: 64x256 tile, fused LN (FFN down, K=1024) ----------------
__global__ void __launch_bounds__(256, 2) gemmln64(GLP p)
{
    extern __shared__ char smc[];
    unsigned sbase = (unsigned)__cvta_generic_to_shared(smc);
    unsigned sA = sbase;
    unsigned sB = sbase + 2 * MABYTES;

    int tid  = threadIdx.x;
    int lane = tid & 31;
    int warp = tid >> 5;
    int wm = warp >> 2, wn = warp & 3;       // wm: 32-row half, wn: 64-col group
    int gid = lane >> 2, tq = lane & 3;
    int l7 = lane & 7;

    int rowBase = blockIdx.y * 64;
    int K = p.K;

    int pr = tid >> 3;
    int pc = tid & 7;
    const __half* Ag = p.A + (size_t)(rowBase + pr) * K + pc * 8;
    const __half* Wg = p.W + (size_t)pr * K + pc * 8;
    unsigned swp = (unsigned)((pc ^ (pr & 7)) << 4);
    unsigned adst0 = sA + (unsigned)(pr * 128) + swp;
    unsigned bdst0 = sB + (unsigned)(pr * 128) + swp;

    auto issue = [&](int s, int k0) {
        unsigned ad = adst0 + (unsigned)(s * MABYTES);
        unsigned bd = bdst0 + (unsigned)(s * LBBYTES);
#pragma unroll
        for (int i = 0; i < 2; i++)
            cpa16(ad + (unsigned)(i * 4096), Ag + (size_t)(32 * i) * K + k0);
#pragma unroll
        for (int i = 0; i < 8; i++)
            cpa16(bd + (unsigned)(i * 4096), Wg + (size_t)(32 * i) * K + k0);
        asm volatile("cp.async.commit_group;");
    };

    int rlocA = lane & 15, hvA = lane >> 4;
    unsigned rowA[2];
#pragma unroll
    for (int mt = 0; mt < 2; mt++)
        rowA[mt] = sA + (unsigned)((wm * 32 + mt * 16 + rlocA) * 128);
    int nrow = ((lane >> 4) & 1) * 8 + l7;
    int hvB = (lane >> 3) & 1;
    unsigned rowB[4];
#pragma unroll
    for (int pp = 0; pp < 4; pp++)
        rowB[pp] = sB + (unsigned)((wn * 64 + pp * 16 + nrow) * 128);

    float c[2][8][4];
#pragma unroll
    for (int i = 0; i < 2; i++)
#pragma unroll
        for (int j = 0; j < 8; j++)
#pragma unroll
            for (int r = 0; r < 4; r++) c[i][j][r] = 0.f;

    int T = K / KC;
    issue(0, 0);

#pragma unroll 1
    for (int t = 0; t < T; t++) {
        asm volatile("cp.async.wait_group 0;");
        __syncthreads();
        if (t + 1 < T) issue((t + 1) & 1, (t + 1) * KC);

        unsigned aoff = (unsigned)((t & 1) * MABYTES);
        unsigned boff = (unsigned)((t & 1) * LBBYTES);

#pragma unroll
        for (int ks = 0; ks < 4; ks++) {
            unsigned swcA = (unsigned)(((2 * ks + hvA) ^ l7) << 4);
            unsigned swcB = (unsigned)(((2 * ks + hvB) ^ l7) << 4);
            unsigned aa[2][4], bb[4][4];
#pragma unroll
            for (int mt = 0; mt < 2; mt++)
                ldsm4(aa[mt][0], aa[mt][1], aa[mt][2], aa[mt][3], rowA[mt] + aoff + swcA);
#pragma unroll
            for (int pp = 0; pp < 4; pp++)
                ldsm4(bb[pp][0], bb[pp][1], bb[pp][2], bb[pp][3], rowB[pp] + boff + swcB);
#pragma unroll
            for (int pp = 0; pp < 4; pp++)
#pragma unroll
                for (int q = 0; q < 2; q++) {
                    int nt = 2 * pp + q;
#pragma unroll
                    for (int mt = 0; mt < 2; mt++)
                        MMA16816(c[mt][nt], aa[mt], bb[pp][2 * q], bb[pp][2 * q + 1]);
                }
        }
        __syncthreads();
    }

    // ---- fused epilogue: bias + residual + LayerNorm over 64 rows ----
    float* red = (float*)smc;
    if (tid < 128) red[tid] = 0.f;
    __syncthreads();

#pragma unroll
    for (int mt = 0; mt < 2; mt++) {
        int rl0 = wm * 32 + mt * 16 + gid;
        int r0 = rowBase + rl0;
        float s0 = 0.f, ss0 = 0.f, s1 = 0.f, ss1 = 0.f;
#pragma unroll
        for (int nt = 0; nt < 8; nt++) {
            int cc = wn * 64 + (nt >> 1) * 16 + (nt & 1) * 8 + tq * 2;
            float b0 = __ldg(p.bias + cc), b1 = __ldg(p.bias + cc + 1);
            float2 x0 = *(const float2*)(p.xres + (size_t)r0 * DM + cc);
            float2 x1 = *(const float2*)(p.xres + (size_t)(r0 + 8) * DM + cc);
            float v0 = c[mt][nt][0] + b0 + x0.x;
            float v1 = c[mt][nt][1] + b1 + x0.y;
            float v2 = c[mt][nt][2] + b0 + x1.x;
            float v3 = c[mt][nt][3] + b1 + x1.y;
            c[mt][nt][0] = v0; c[mt][nt][1] = v1; c[mt][nt][2] = v2; c[mt][nt][3] = v3;
            s0 += v0 + v1; ss0 += v0 * v0 + v1 * v1;
            s1 += v2 + v3; ss1 += v2 * v2 + v3 * v3;
        }
#pragma unroll
        for (int o = 1; o <= 2; o <<= 1) {
            s0  += __shfl_xor_sync(0xffffffffu, s0, o);
            ss0 += __shfl_xor_sync(0xffffffffu, ss0, o);
            s1  += __shfl_xor_sync(0xffffffffu, s1, o);
            ss1 += __shfl_xor_sync(0xffffffffu, ss1, o);
        }
        if (tq == 0) {
            atomicAdd(&red[2 * rl0], s0);
            atomicAdd(&red[2 * rl0 + 1], ss0);
            atomicAdd(&red[2 * (rl0 + 8)], s1);
            atomicAdd(&red[2 * (rl0 + 8) + 1], ss1);
        }
    }
    __syncthreads();

    int mode = p.mode;
#pragma unroll
    for (int mt = 0; mt < 2; mt++) {
        int rl0 = wm * 32 + mt * 16 + gid;
        int r0 = rowBase + rl0;
        float mean0 = red[2 * rl0] * (1.0f / DM);
        float var0  = red[2 * rl0 + 1] * (1.0f / DM) - mean0 * mean0;
        float rstd0 = rsqrtf(var0 + 1e-5f);
        float mean1 = red[2 * (rl0 + 8)] * (1.0f / DM);
        float var1  = red[2 * (rl0 + 8) + 1] * (1.0f / DM) - mean1 * mean1;
        float rstd1 = rsqrtf(var1 + 1e-5f);
#pragma unroll
        for (int nt = 0; nt < 8; nt++) {
            int cc = wn * 64 + (nt >> 1) * 16 + (nt & 1) * 8 + tq * 2;
            float gg0 = __ldg(p.g + cc), gg1 = __ldg(p.g + cc + 1);
            float bb0 = __ldg(p.be + cc), bb1 = __ldg(p.be + cc + 1);
            float v0 = (c[mt][nt][0] - mean0) * rstd0 * gg0 + bb0;
            float v1 = (c[mt][nt][1] - mean0) * rstd0 * gg1 + bb1;
            float v2 = (c[mt][nt][2] - mean1) * rstd1 * gg0 + bb0;
            float v3 = (c[mt][nt][3] - mean1) * rstd1 * gg1 + bb1;
            size_t o0 = (size_t)r0 * DM + cc;
            size_t o1 = (size_t)(r0 + 8) * DM + cc;
            if (mode == 5) {
                *(float2*)(p.xout + o0) = make_float2(v0, v1);
                *(float2*)(p.xout + o1) = make_float2(v2, v3);
            } else {
                *(float2*)(p.xout + o0) = make_float2(v0, v1);
                *(float2*)(p.xout + o1) = make_float2(v2, v3);
                *(__half2*)(p.xh + o0) = __floats2half2_rn(v0, v1);
                *(__half2*)(p.xh + o1) = __floats2half2_rn(v2, v3);
                if (mode == 4) {
                    float2 p0 = *(const float2*)(p.pos + o0);
                    float2 p1 = *(const float2*)(p.pos + o1);
                    *(__half2*)(p.qh + o0) = __floats2half2_rn(v0 + p0.x, v1 + p0.y);
                    *(__half2*)(p.qh + o1) = __floats2half2_rn(v2 + p1.x, v3 + p1.y);
                }
            }
        }
    }
}

// ---------------- deformable sampling: dual-point lanes, half2 loads ----------------
__global__ void __launch_bounds__(256) sample_kernel(
    const __half* __restrict__ value, const float* __restrict__ offaw,
    const float* __restrict__ ref, __half* __restrict__ attnh)
{
    int row = blockIdx.x;
    int h = threadIdx.x >> 5;
    int lane = threadIdx.x & 31;
    int grp = lane >> 4;
    int lc  = lane & 15;
    int n = row / LEN;

    float offv = offaw[(size_t)row * NQ + h * 32 + lane];
    float awraw = (lane < 16) ? offaw[(size_t)row * NQ + 256 + h * 16 + lane] : -1e30f;
    float refv = (lane < 8)  ? ref[(size_t)row * 8 + lane] : 0.f;

    float mx = awraw;
#pragma unroll
    for (int o = 8; o; o >>= 1) mx = fmaxf(mx, __shfl_xor_sync(0xffffffffu, mx, o, 16));
    float e = (lane < 16) ? expf(awraw - mx) : 0.f;
    float ssum = e;
#pragma unroll
    for (int o = 8; o; o >>= 1) ssum += __shfl_xor_sync(0xffffffffu, ssum, o, 16);
    float awv = e / ssum;

    const __half* vbase = value + (size_t)n * LEN * 256 + h * 32 + lc * 2;
    float accx = 0.f, accy = 0.f;
#pragma unroll
    for (int i = 0; i < 8; i++) {
        int p = grp * 8 + i;
        int lvl = p >> 2;
        float ox = __shfl_sync(0xffffffffu, offv, 2 * p);
        float oy = __shfl_sync(0xffffffffu, offv, 2 * p + 1);
        float a  = __shfl_sync(0xffffffffu, awv, p);
        float rx = __shfl_sync(0xffffffffu, refv, 2 * lvl);
        float ry = __shfl_sync(0xffffffffu, refv, 2 * lvl + 1);
        int HW = c_HW[lvl], s = c_S[lvl];
        float fw = (float)HW;
        float xf = (rx + ox / fw) * fw - 0.5f;
        float yf = (ry + oy / fw) * fw - 0.5f;
        float x0f = floorf(xf), y0f = floorf(yf);
        int ix = (int)x0f, iy = (int)y0f;
        float wx1 = xf - x0f, wy1 = yf - y0f;
        float wx0 = 1.f - wx1, wy0 = 1.f - wy1;
        const __half* vb = vbase + (size_t)s * 256;
        bool xin0 = (ix >= 0) && (ix < HW);
        bool xin1 = (ix + 1 >= 0) && (ix + 1 < HW);
        bool yin0 = (iy >= 0) && (iy < HW);
        bool yin1 = (iy + 1 >= 0) && (iy + 1 < HW);
        float sx = 0.f, sy = 0.f;
        if (xin0 && yin0) {
            float2 v = __half22float2(*(const __half2*)(vb + (size_t)(iy * HW + ix) * 256));
            float w = wx0 * wy0; sx += w * v.x; sy += w * v.y;
        }
        if (xin1 && yin0) {
            float2 v = __half22float2(*(const __half2*)(vb + (size_t)(iy * HW + ix + 1) * 256));
            float w = wx1 * wy0; sx += w * v.x; sy += w * v.y;
        }
        if (xin0 && yin1) {
            float2 v = __half22float2(*(const __half2*)(vb + (size_t)((iy + 1) * HW + ix) * 256));
            float w = wx0 * wy1; sx += w * v.x; sy += w * v.y;
        }
        if (xin1 && yin1) {
            float2 v = __half22float2(*(const __half2*)(vb + (size_t)((iy + 1) * HW + ix + 1) * 256));
            float w = wx1 * wy1; sx += w * v.x; sy += w * v.y;
        }
        accx += a * sx;
        accy += a * sy;
    }
    accx += __shfl_down_sync(0xffffffffu, accx, 16);
    accy += __shfl_down_sync(0xffffffffu, accy, 16);
    if (lane < 16)
        *(__half2*)(attnh + (size_t)row * 256 + h * 32 + lc * 2) = __floats2half2_rn(accx, accy);
}

// ---------------- launch ----------------
extern "C" void kernel_launch(void* const* d_in, const int* in_sizes, int n_in,
                              void* d_out, int out_size)
{
    (void)in_sizes; (void)n_in; (void)out_size;
    const float* src  = (const float*)d_in[0];
    const float* pos  = (const float*)d_in[1];
    const float* vr   = (const float*)d_in[2];
    const float* Wv   = (const float*)d_in[3];
    const float* bv   = (const float*)d_in[4];
    const float* Woff = (const float*)d_in[5];
    const float* boff = (const float*)d_in[6];
    const float* Wa   = (const float*)d_in[7];
    const float* ba   = (const float*)d_in[8];
    const float* Wo   = (const float*)d_in[9];
    const float* bo   = (const float*)d_in[10];
    const float* g1   = (const float*)d_in[11];
    const float* be1  = (const float*)d_in[12];
    const float* Wl1  = (const float*)d_in[13];
    const float* bl1  = (const float*)d_in[14];
    const float* Wl2  = (const float*)d_in[15];
    const float* bl2  = (const float*)d_in[16];
    const float* g2   = (const float*)d_in[17];
    const float* be2  = (const float*)d_in[18];
    float* out = (float*)d_out;

    float *x, *offaw, *ref, *bq;
    __half *xh, *qh, *valh, *attnh, *ffnh;
    __half *wvh, *wqh, *woh, *wl1h, *wl2h;
    cudaGetSymbolAddress((void**)&x,     g_x);
    cudaGetSymbolAddress((void**)&xh,    g_xh);
    cudaGetSymbolAddress((void**)&qh,    g_qh);
    cudaGetSymbolAddress((void**)&valh,  g_valh);
    cudaGetSymbolAddress((void**)&offaw, g_offaw);
    cudaGetSymbolAddress((void**)&attnh, g_attnh);
    cudaGetSymbolAddress((void**)&ffnh,  g_ffnh);
    cudaGetSymbolAddress((void**)&ref,   g_ref);
    cudaGetSymbolAddress((void**)&wvh,   g_wvh);
    cudaGetSymbolAddress((void**)&wqh,   g_wqh);
    cudaGetSymbolAddress((void**)&woh,   g_woh);
    cudaGetSymbolAddress((void**)&wl1h,  g_wl1h);
    cudaGetSymbolAddress((void**)&wl2h,  g_wl2h);
    cudaGetSymbolAddress((void**)&bq,    g_bq);

    cudaFuncSetAttribute(gemmk,    cudaFuncAttributeMaxDynamicSharedMemorySize, SMEMG);
    cudaFuncSetAttribute(gemmln,   cudaFuncAttributeMaxDynamicSharedMemorySize, SMEML);
    cudaFuncSetAttribute(gemmln64, cudaFuncAttributeMaxDynamicSharedMemorySize, SMEM64);

    pre_kernel<<<NCVT + NINIT + NREF, 256>>>(Wv, Woff, Wa, Wo, Wl1, Wl2, boff, ba,
                                             wvh, wqh, woh, wl1h, wl2h, bq,
                                             src, pos, x, xh, qh, vr, ref);

    dim3 gMerged(DM / TN + NQ / TN, MROWS / TM);   // (5, 85)
    dim3 gFF(DFFN / TN, MROWS / TM);               // (8, 85)
    dim3 gLN(1, MROWS / 32);                       // (1, 340)
    dim3 gLN64(1, MROWS / 64);                     // (1, 170)

    for (int l = 0; l < NLAYERS; l++) {
        GP pv  { xh, wvh + (size_t)l * DM * DM, bv + l * DM, valh, DM, DM, 1 };
        GP pq  { qh, wqh + (size_t)l * NQ * DM, bq + l * NQ, offaw, DM, NQ, 0 };
        gemmk<<<gMerged, 256, SMEMG>>>(pv, pq, DM / TN);

        sample_kernel<<<MROWS, 256>>>(valh, offaw, ref, attnh);

        GLP po { attnh, woh + (size_t)l * DM * DM, bo + l * DM,
                 g1 + l * DM, be1 + l * DM, pos, x, x, xh, qh, DM, 3 };
        gemmln<<<gLN, 256, SMEML>>>(po);

        GP pf1 { xh, wl1h + (size_t)l * DM * DFFN, bl1 + l * DFFN, ffnh, DM, DFFN, 2 };
        gemmk<<<gFF, 256, SMEMG>>>(pf1, pf1, gFF.x);

        bool last = (l == NLAYERS - 1);
        GLP pf2 { ffnh, wl2h + (size_t)l * DFFN * DM, bl2 + l * DM,
                  g2 + l * DM, be2 + l * DM, pos, x,
                  last ? out : x, xh, qh, DFFN, last ? 5 : 4 };
        gemmln64<<<gLN64, 256, SMEM64>>>(pf2);
    }
}

// round 15
// speedup vs baseline: 1.0257x; 1.0257x over previous
#include <cuda_runtime.h>
#include <cuda_fp16.h>
#include <math.h>

#define LEN 5440
#define NBATCH 2
#define MROWS (NBATCH*LEN)   /* 10880 */
#define DM 256
#define NH 8
#define DFFN 1024
#define NLAYERS 2
#define NQ 384

// gemmk tile: 128 x 128, K-chunk 64, 3-stage
#define TM 128
#define TN 128
#define KC 64
#define NSTAGE 3
#define ABYTES 16384
#define BBYTES 16384
#define SMEMG (NSTAGE*(ABYTES+BBYTES))   /* 98304 */

// gemmln tile: 32 x 256, 2-stage
#define LABYTES (32*128)     /* 4096 */
#define LBBYTES (256*128)    /* 32768 */
#define SMEML (2*(LABYTES+LBBYTES))   /* 73728 */

// preamble block ranges
#define NCVT (NLAYERS*737)         /* 1474 */
#define NINIT ((MROWS*DM+255)/256) /* 10880 */
#define NREF  ((MROWS+255)/256)    /* 43 */

__constant__ int c_HW[4] = {64, 32, 16, 8};
__constant__ int c_S[4]  = {0, 4096, 5120, 5376};

// ---------------- scratch ----------------
__device__ __align__(16) float  g_x[MROWS * DM];
__device__ __align__(16) __half g_xh[MROWS * DM];
__device__ __align__(16) __half g_qh[MROWS * DM];
__device__ __align__(16) __half g_valh[MROWS * DM];
__device__ __align__(16) float  g_offaw[MROWS * NQ];
__device__ __align__(16) __half g_attnh[MROWS * DM];
__device__ __align__(16) __half g_ffnh[MROWS * DFFN];
__device__ __align__(16) float  g_ref[MROWS * 8];
__device__ __align__(16) __half g_wvh[NLAYERS * DM * DM];
__device__ __align__(16) __half g_wqh[NLAYERS * NQ * DM];
__device__ __align__(16) __half g_woh[NLAYERS * DM * DM];
__device__ __align__(16) __half g_wl1h[NLAYERS * DM * DFFN];
__device__ __align__(16) __half g_wl2h[NLAYERS * DFFN * DM];
__device__ __align__(16) float  g_bq[NLAYERS * NQ];

// ---------------- helpers ----------------
__device__ __forceinline__ void cpa16(unsigned saddr, const void* g) {
    asm volatile("cp.async.cg.shared.global [%0], [%1], 16;" :: "r"(saddr), "l"(g));
}
__device__ __forceinline__ void ldsm4(unsigned& r0, unsigned& r1, unsigned& r2, unsigned& r3,
                                      unsigned addr) {
    asm volatile("ldmatrix.sync.aligned.m8n8.x4.shared.b16 {%0,%1,%2,%3}, [%4];"
                 : "=r"(r0), "=r"(r1), "=r"(r2), "=r"(r3) : "r"(addr));
}
#define MMA16816(C, A, B0, B1) \
    asm volatile("mma.sync.aligned.m16n8k16.row.col.f32.f16.f16.f32 " \
                 "{%0,%1,%2,%3}, {%4,%5,%6,%7}, {%8,%9}, {%0,%1,%2,%3};\n" \
                 : "+f"((C)[0]), "+f"((C)[1]), "+f"((C)[2]), "+f"((C)[3]) \
                 : "r"((A)[0]), "r"((A)[1]), "r"((A)[2]), "r"((A)[3]), "r"(B0), "r"(B1))

// ---------------- merged preamble: weight cvt+transpose | init | refpts ----------------
__global__ void pre_kernel(
    const float* __restrict__ Wv, const float* __restrict__ Woff, const float* __restrict__ Wa,
    const float* __restrict__ Wo, const float* __restrict__ Wl1, const float* __restrict__ Wl2,
    const float* __restrict__ boff, const float* __restrict__ ba,
    __half* __restrict__ wvh, __half* __restrict__ wqh, __half* __restrict__ woh,
    __half* __restrict__ wl1h, __half* __restrict__ wl2h, float* __restrict__ bq,
    const float* __restrict__ src, const float* __restrict__ pos,
    float* __restrict__ x, __half* __restrict__ xh, __half* __restrict__ qh,
    const float* __restrict__ vr, float* __restrict__ ref)
{
    __shared__ float tile[32][33];
    int b = blockIdx.x;
    int tid = threadIdx.x;

    if (b >= NCVT + NINIT) {                 // ---- refpts ----
        int idx = (b - NCVT - NINIT) * 256 + tid;
        if (idx >= MROWS) return;
        int n = idx / LEN, t = idx % LEN;
        int lvl = 3;
        if (t < 4096) lvl = 0; else if (t < 5120) lvl = 1; else if (t < 5376) lvl = 2;
        int s = c_S[lvl], hw = c_HW[lvl];
        int local = t - s;
        int i = local / hw, j = local % hw;
        float ry = (i + 0.5f) / (vr[(n * 4 + lvl) * 2 + 1] * (float)hw);
        float rx = (j + 0.5f) / (vr[(n * 4 + lvl) * 2 + 0] * (float)hw);
#pragma unroll
        for (int l2 = 0; l2 < 4; l2++) {
            ref[idx * 8 + l2 * 2 + 0] = rx * vr[(n * 4 + l2) * 2 + 0];
            ref[idx * 8 + l2 * 2 + 1] = ry * vr[(n * 4 + l2) * 2 + 1];
        }
        return;
    }
    if (b >= NCVT) {                          // ---- init ----
        int i = (b - NCVT) * 256 + tid;
        float s = src[i];
        x[i] = s;
        xh[i] = __float2half_rn(s);
        qh[i] = __float2half_rn(s + pos[i]);
        return;
    }
    // ---- weight convert + transpose ----
    int l = b / 737, r = b % 737;
    int tx = tid & 31, ty = tid >> 5;
    if (r == 736) {
        for (int i = tid; i < NQ; i += 256)
            bq[l * NQ + i] = (i < 256) ? boff[l * 256 + i] : ba[l * 128 + i - 256];
        return;
    }
    const float* srcw; __half* dst; int K, N, t, rowOff = 0;
    if (r < 64)       { srcw = Wv   + (size_t)l * 256 * 256;  dst = wvh  + (size_t)l * 256 * 256;  K = 256;  N = 256;  t = r; }
    else if (r < 128) { srcw = Woff + (size_t)l * 256 * 256;  dst = wqh  + (size_t)l * NQ * 256;   K = 256;  N = 256;  t = r - 64; }
    else if (r < 160) { srcw = Wa   + (size_t)l * 256 * 128;  dst = wqh  + (size_t)l * NQ * 256;   K = 256;  N = 128;  t = r - 128; rowOff = 256; }
    else if (r < 224) { srcw = Wo   + (size_t)l * 256 * 256;  dst = woh  + (size_t)l * 256 * 256;  K = 256;  N = 256;  t = r - 160; }
    else if (r < 480) { srcw = Wl1  + (size_t)l * 256 * 1024; dst = wl1h + (size_t)l * 256 * 1024; K = 256;  N = 1024; t = r - 224; }
    else              { srcw = Wl2  + (size_t)l * 1024 * 256; dst = wl2h + (size_t)l * 1024 * 256; K = 1024; N = 256;  t = r - 480; }
    int tn = t % (N / 32), tk = t / (N / 32);
    int k0 = tk * 32, n0 = tn * 32;
#pragma unroll
    for (int i = ty; i < 32; i += 8)
        tile[i][tx] = srcw[(size_t)(k0 + i) * N + n0 + tx];
    __syncthreads();
#pragma unroll
    for (int i = ty; i < 32; i += 8)
        dst[(size_t)(rowOff + n0 + i) * K + k0 + tx] = __float2half_rn(tile[tx][i]);
}

// ---------------- gemmk: 128x128 tile, 3-stage ----------------
struct GP {
    const __half* A; const __half* W; const float* bias; void* C;
    int K; int Nc; int mode;
};

__global__ void __launch_bounds__(256, 2) gemmk(GP p0, GP p1, int split)
{
    extern __shared__ char smc[];
    unsigned sbase = (unsigned)__cvta_generic_to_shared(smc);
    unsigned sA = sbase;
    unsigned sB = sbase + NSTAGE * ABYTES;

    GP p; int bx = blockIdx.x;
    if (bx < split) p = p0; else { p = p1; bx -= split; }

    int tid  = threadIdx.x;
    int lane = tid & 31;
    int warp = tid >> 5;
    int wm = warp >> 2, wn = warp & 3;
    int gid = lane >> 2, tq = lane & 3;
    int l7 = lane & 7;

    int rowBase = blockIdx.y * TM;
    int colBase = bx * TN;
    int K = p.K;

    int pr = tid >> 3;
    int pc = tid & 7;
    const __half* Ag = p.A + (size_t)(rowBase + pr) * K + pc * 8;
    const __half* Wg = p.W + (size_t)(colBase + pr) * K + pc * 8;
    unsigned swp = (unsigned)((pc ^ (pr & 7)) << 4);
    unsigned adst0 = sA + (unsigned)(pr * 128) + swp;
    unsigned bdst0 = sB + (unsigned)(pr * 128) + swp;

    auto issue = [&](int s, int k0) {
        unsigned ad = adst0 + (unsigned)(s * ABYTES);
        unsigned bd = bdst0 + (unsigned)(s * BBYTES);
#pragma unroll
        for (int i = 0; i < 4; i++) {
            cpa16(ad + (unsigned)(i * 4096), Ag + (size_t)(32 * i) * K + k0);
            cpa16(bd + (unsigned)(i * 4096), Wg + (size_t)(32 * i) * K + k0);
        }
        asm volatile("cp.async.commit_group;");
    };

    int rlocA = lane & 15, hvA = lane >> 4;
    unsigned rowA[4];
#pragma unroll
    for (int mt = 0; mt < 4; mt++)
        rowA[mt] = sA + (unsigned)((wm * 64 + mt * 16 + rlocA) * 128);
    int nrow = ((lane >> 4) & 1) * 8 + l7;
    int hvB = (lane >> 3) & 1;
    unsigned rowB[2];
#pragma unroll
    for (int pp = 0; pp < 2; pp++)
        rowB[pp] = sB + (unsigned)((wn * 32 + pp * 16 + nrow) * 128);

    float c[4][4][4];
#pragma unroll
    for (int i = 0; i < 4; i++)
#pragma unroll
        for (int j = 0; j < 4; j++)
#pragma unroll
            for (int r = 0; r < 4; r++) c[i][j][r] = 0.f;

    int T = K / KC;
    issue(0, 0);
    issue(1, KC);

#pragma unroll 1
    for (int t = 0; t < T; t++) {
        asm volatile("cp.async.wait_group 1;");
        __syncthreads();
        if (t + 2 < T) issue((t + 2) % NSTAGE, (t + 2) * KC);
        else asm volatile("cp.async.commit_group;");

        unsigned aoff = (unsigned)((t % NSTAGE) * ABYTES);
        unsigned boff = (unsigned)((t % NSTAGE) * BBYTES);

#pragma unroll
        for (int ks = 0; ks < 4; ks++) {
            unsigned swcA = (unsigned)(((2 * ks + hvA) ^ l7) << 4);
            unsigned swcB = (unsigned)(((2 * ks + hvB) ^ l7) << 4);
            unsigned aa[4][4], bb[2][4];
#pragma unroll
            for (int mt = 0; mt < 4; mt++)
                ldsm4(aa[mt][0], aa[mt][1], aa[mt][2], aa[mt][3], rowA[mt] + aoff + swcA);
#pragma unroll
            for (int pp = 0; pp < 2; pp++)
                ldsm4(bb[pp][0], bb[pp][1], bb[pp][2], bb[pp][3], rowB[pp] + boff + swcB);
#pragma unroll
            for (int pp = 0; pp < 2; pp++)
#pragma unroll
                for (int q = 0; q < 2; q++) {
                    int nt = 2 * pp + q;
#pragma unroll
                    for (int mt = 0; mt < 4; mt++)
                        MMA16816(c[mt][nt], aa[mt], bb[pp][2 * q], bb[pp][2 * q + 1]);
                }
        }
        // no trailing sync: next iteration's top sync orders stage reuse
    }

    int Nc = p.Nc, mode = p.mode;
#pragma unroll
    for (int mt = 0; mt < 4; mt++) {
#pragma unroll
        for (int nt = 0; nt < 4; nt++) {
            int r0 = rowBase + wm * 64 + mt * 16 + gid;
            int cc = colBase + wn * 32 + nt * 8 + tq * 2;
            float b0v = p.bias[cc], b1v = p.bias[cc + 1];
            float v0 = c[mt][nt][0] + b0v, v1 = c[mt][nt][1] + b1v;
            float v2 = c[mt][nt][2] + b0v, v3 = c[mt][nt][3] + b1v;
            if (mode == 0) {
                float* C = (float*)p.C;
                *(float2*)(C + (size_t)r0 * Nc + cc)       = make_float2(v0, v1);
                *(float2*)(C + (size_t)(r0 + 8) * Nc + cc) = make_float2(v2, v3);
            } else {
                if (mode == 2) {
                    v0 = fmaxf(v0, 0.f); v1 = fmaxf(v1, 0.f);
                    v2 = fmaxf(v2, 0.f); v3 = fmaxf(v3, 0.f);
                }
                __half* C = (__half*)p.C;
                *(__half2*)(C + (size_t)r0 * Nc + cc)       = __floats2half2_rn(v0, v1);
                *(__half2*)(C + (size_t)(r0 + 8) * Nc + cc) = __floats2half2_rn(v2, v3);
            }
        }
    }
}

// ---------------- gemmln: 32x256 tile, fused bias+residual+LayerNorm ----------------
// mode: 3 = write x + xh ; 4 = write x + xh + qh ; 5 = final, write out only.
struct GLP {
    const __half* A; const __half* W; const float* bias;
    const float* g; const float* be; const float* pos;
    const float* xres; float* xout; __half* xh; __half* qh;
    int K; int mode;
};

__global__ void __launch_bounds__(256, 3) gemmln(GLP p)
{
    extern __shared__ char smc[];
    unsigned sbase = (unsigned)__cvta_generic_to_shared(smc);
    unsigned sA = sbase;
    unsigned sB = sbase + 2 * LABYTES;

    int tid  = threadIdx.x;
    int lane = tid & 31;
    int wn   = tid >> 5;            // warp = 32-col group 0..7
    int gid = lane >> 2, tq = lane & 3;
    int l7 = lane & 7;

    int rowBase = blockIdx.y * 32;
    int K = p.K;

    int pr = tid >> 3;              // 0..31
    int pc = tid & 7;
    const __half* Ag = p.A + (size_t)(rowBase + pr) * K + pc * 8;
    const __half* Wg = p.W + (size_t)pr * K + pc * 8;
    unsigned swp = (unsigned)((pc ^ (pr & 7)) << 4);
    unsigned adst0 = sA + (unsigned)(pr * 128) + swp;
    unsigned bdst0 = sB + (unsigned)(pr * 128) + swp;

    auto issue = [&](int s, int k0) {
        cpa16(adst0 + (unsigned)(s * LABYTES), Ag + k0);
        unsigned bd = bdst0 + (unsigned)(s * LBBYTES);
#pragma unroll
        for (int i = 0; i < 8; i++)
            cpa16(bd + (unsigned)(i * 4096), Wg + (size_t)(32 * i) * K + k0);
        asm volatile("cp.async.commit_group;");
    };

    int rlocA = lane & 15, hvA = lane >> 4;
    unsigned rowA[2];
#pragma unroll
    for (int mt = 0; mt < 2; mt++)
        rowA[mt] = sA + (unsigned)((mt * 16 + rlocA) * 128);
    int nrow = ((lane >> 4) & 1) * 8 + l7;
    int hvB = (lane >> 3) & 1;
    unsigned rowB[2];
#pragma unroll
    for (int pp = 0; pp < 2; pp++)
        rowB[pp] = sB + (unsigned)((wn * 32 + pp * 16 + nrow) * 128);

    float c[2][4][4];
#pragma unroll
    for (int i = 0; i < 2; i++)
#pragma unroll
        for (int j = 0; j < 4; j++)
#pragma unroll
            for (int r = 0; r < 4; r++) c[i][j][r] = 0.f;

    int T = K / KC;
    issue(0, 0);

#pragma unroll 1
    for (int t = 0; t < T; t++) {
        asm volatile("cp.async.wait_group 0;");
        __syncthreads();
        if (t + 1 < T) issue((t + 1) & 1, (t + 1) * KC);

        unsigned aoff = (unsigned)((t & 1) * LABYTES);
        unsigned boff = (unsigned)((t & 1) * LBBYTES);

#pragma unroll
        for (int ks = 0; ks < 4; ks++) {
            unsigned swcA = (unsigned)(((2 * ks + hvA) ^ l7) << 4);
            unsigned swcB = (unsigned)(((2 * ks + hvB) ^ l7) << 4);
            unsigned aa[2][4], bb[2][4];
#pragma unroll
            for (int mt = 0; mt < 2; mt++)
                ldsm4(aa[mt][0], aa[mt][1], aa[mt][2], aa[mt][3], rowA[mt] + aoff + swcA);
#pragma unroll
            for (int pp = 0; pp < 2; pp++)
                ldsm4(bb[pp][0], bb[pp][1], bb[pp][2], bb[pp][3], rowB[pp] + boff + swcB);
#pragma unroll
            for (int pp = 0; pp < 2; pp++)
#pragma unroll
                for (int q = 0; q < 2; q++) {
                    int nt = 2 * pp + q;
#pragma unroll
                    for (int mt = 0; mt < 2; mt++)
                        MMA16816(c[mt][nt], aa[mt], bb[pp][2 * q], bb[pp][2 * q + 1]);
                }
        }
        __syncthreads();
    }

    // ---- fused epilogue: bias + residual, LayerNorm per row ----
    float* red = (float*)smc;   // 32 rows x (sum, sumsq)
    if (tid < 64) red[tid] = 0.f;
    __syncthreads();

#pragma unroll
    for (int mt = 0; mt < 2; mt++) {
        int rl0 = mt * 16 + gid;
        int r0 = rowBase + rl0;
        float s0 = 0.f, ss0 = 0.f, s1 = 0.f, ss1 = 0.f;
#pragma unroll
        for (int nt = 0; nt < 4; nt++) {
            int cc = wn * 32 + nt * 8 + tq * 2;
            float b0 = __ldg(p.bias + cc), b1 = __ldg(p.bias + cc + 1);
            float2 x0 = *(const float2*)(p.xres + (size_t)r0 * DM + cc);
            float2 x1 = *(const float2*)(p.xres + (size_t)(r0 + 8) * DM + cc);
            float v0 = c[mt][nt][0] + b0 + x0.x;
            float v1 = c[mt][nt][1] + b1 + x0.y;
            float v2 = c[mt][nt][2] + b0 + x1.x;
            float v3 = c[mt][nt][3] + b1 + x1.y;
            c[mt][nt][0] = v0; c[mt][nt][1] = v1; c[mt][nt][2] = v2; c[mt][nt][3] = v3;
            s0 += v0 + v1; ss0 += v0 * v0 + v1 * v1;
            s1 += v2 + v3; ss1 += v2 * v2 + v3 * v3;
        }
#pragma unroll
        for (int o = 1; o <= 2; o <<= 1) {
            s0  += __shfl_xor_sync(0xffffffffu, s0, o);
            ss0 += __shfl_xor_sync(0xffffffffu, ss0, o);
            s1  += __shfl_xor_sync(0xffffffffu, s1, o);
            ss1 += __shfl_xor_sync(0xffffffffu, ss1, o);
        }
        if (tq == 0) {
            atomicAdd(&red[2 * rl0], s0);
            atomicAdd(&red[2 * rl0 + 1], ss0);
            atomicAdd(&red[2 * (rl0 + 8)], s1);
            atomicAdd(&red[2 * (rl0 + 8) + 1], ss1);
        }
    }
    __syncthreads();

    int mode = p.mode;
#pragma unroll
    for (int mt = 0; mt < 2; mt++) {
        int rl0 = mt * 16 + gid;
        int r0 = rowBase + rl0;
        float mean0 = red[2 * rl0] * (1.0f / DM);
        float var0  = red[2 * rl0 + 1] * (1.0f / DM) - mean0 * mean0;
        float rstd0 = rsqrtf(var0 + 1e-5f);
        float mean1 = red[2 * (rl0 + 8)] * (1.0f / DM);
        float var1  = red[2 * (rl0 + 8) + 1] * (1.0f / DM) - mean1 * mean1;
        float rstd1 = rsqrtf(var1 + 1e-5f);
#pragma unroll
        for (int nt = 0; nt < 4; nt++) {
            int cc = wn * 32 + nt * 8 + tq * 2;
            float gg0 = __ldg(p.g + cc), gg1 = __ldg(p.g + cc + 1);
            float bb0 = __ldg(p.be + cc), bb1 = __ldg(p.be + cc + 1);
            float v0 = (c[mt][nt][0] - mean0) * rstd0 * gg0 + bb0;
            float v1 = (c[mt][nt][1] - mean0) * rstd0 * gg1 + bb1;
            float v2 = (c[mt][nt][2] - mean1) * rstd1 * gg0 + bb0;
            float v3 = (c[mt][nt][3] - mean1) * rstd1 * gg1 + bb1;
            size_t o0 = (size_t)r0 * DM + cc;
            size_t o1 = (size_t)(r0 + 8) * DM + cc;
            if (mode == 5) {
                *(float2*)(p.xout + o0) = make_float2(v0, v1);
                *(float2*)(p.xout + o1) = make_float2(v2, v3);
            } else {
                *(float2*)(p.xout + o0) = make_float2(v0, v1);
                *(float2*)(p.xout + o1) = make_float2(v2, v3);
                *(__half2*)(p.xh + o0) = __floats2half2_rn(v0, v1);
                *(__half2*)(p.xh + o1) = __floats2half2_rn(v2, v3);
                if (mode == 4) {
                    float2 p0 = *(const float2*)(p.pos + o0);
                    float2 p1 = *(const float2*)(p.pos + o1);
                    *(__half2*)(p.qh + o0) = __floats2half2_rn(v0 + p0.x, v1 + p0.y);
                    *(__half2*)(p.qh + o1) = __floats2half2_rn(v2 + p1.x, v3 + p1.y);
                }
            }
        }
    }
}

// ---------------- deformable sampling: dual-point lanes, half2 loads ----------------
__global__ void __launch_bounds__(256) sample_kernel(
    const __half* __restrict__ value, const float* __restrict__ offaw,
    const float* __restrict__ ref, __half* __restrict__ attnh)
{
    int row = blockIdx.x;
    int h = threadIdx.x >> 5;
    int lane = threadIdx.x & 31;
    int grp = lane >> 4;
    int lc  = lane & 15;
    int n = row / LEN;

    float offv = offaw[(size_t)row * NQ + h * 32 + lane];
    float awraw = (lane < 16) ? offaw[(size_t)row * NQ + 256 + h * 16 + lane] : -1e30f;
    float refv = (lane < 8)  ? ref[(size_t)row * 8 + lane] : 0.f;

    float mx = awraw;
#pragma unroll
    for (int o = 8; o; o >>= 1) mx = fmaxf(mx, __shfl_xor_sync(0xffffffffu, mx, o, 16));
    float e = (lane < 16) ? expf(awraw - mx) : 0.f;
    float ssum = e;
#pragma unroll
    for (int o = 8; o; o >>= 1) ssum += __shfl_xor_sync(0xffffffffu, ssum, o, 16);
    float awv = e / ssum;

    const __half* vbase = value + (size_t)n * LEN * 256 + h * 32 + lc * 2;
    float accx = 0.f, accy = 0.f;
#pragma unroll
    for (int i = 0; i < 8; i++) {
        int p = grp * 8 + i;
        int lvl = p >> 2;
        float ox = __shfl_sync(0xffffffffu, offv, 2 * p);
        float oy = __shfl_sync(0xffffffffu, offv, 2 * p + 1);
        float a  = __shfl_sync(0xffffffffu, awv, p);
        float rx = __shfl_sync(0xffffffffu, refv, 2 * lvl);
        float ry = __shfl_sync(0xffffffffu, refv, 2 * lvl + 1);
        int HW = c_HW[lvl], s = c_S[lvl];
        float fw = (float)HW;
        float xf = (rx + ox / fw) * fw - 0.5f;
        float yf = (ry + oy / fw) * fw - 0.5f;
        float x0f = floorf(xf), y0f = floorf(yf);
        int ix = (int)x0f, iy = (int)y0f;
        float wx1 = xf - x0f, wy1 = yf - y0f;
        float wx0 = 1.f - wx1, wy0 = 1.f - wy1;
        const __half* vb = vbase + (size_t)s * 256;
        bool xin0 = (ix >= 0) && (ix < HW);
        bool xin1 = (ix + 1 >= 0) && (ix + 1 < HW);
        bool yin0 = (iy >= 0) && (iy < HW);
        bool yin1 = (iy + 1 >= 0) && (iy + 1 < HW);
        float sx = 0.f, sy = 0.f;
        if (xin0 && yin0) {
            float2 v = __half22float2(*(const __half2*)(vb + (size_t)(iy * HW + ix) * 256));
            float w = wx0 * wy0; sx += w * v.x; sy += w * v.y;
        }
        if (xin1 && yin0) {
            float2 v = __half22float2(*(const __half2*)(vb + (size_t)(iy * HW + ix + 1) * 256));
            float w = wx1 * wy0; sx += w * v.x; sy += w * v.y;
        }
        if (xin0 && yin1) {
            float2 v = __half22float2(*(const __half2*)(vb + (size_t)((iy + 1) * HW + ix) * 256));
            float w = wx0 * wy1; sx += w * v.x; sy += w * v.y;
        }
        if (xin1 && yin1) {
            float2 v = __half22float2(*(const __half2*)(vb + (size_t)((iy + 1) * HW + ix + 1) * 256));
            float w = wx1 * wy1; sx += w * v.x; sy += w * v.y;
        }
        accx += a * sx;
        accy += a * sy;
    }
    accx += __shfl_down_sync(0xffffffffu, accx, 16);
    accy += __shfl_down_sync(0xffffffffu, accy, 16);
    if (lane < 16)
        *(__half2*)(attnh + (size_t)row * 256 + h * 32 + lc * 2) = __floats2half2_rn(accx, accy);
}

// ---------------- launch ----------------
extern "C" void kernel_launch(void* const* d_in, const int* in_sizes, int n_in,
                              void* d_out, int out_size)
{
    (void)in_sizes; (void)n_in; (void)out_size;
    const float* src  = (const float*)d_in[0];
    const float* pos  = (const float*)d_in[1];
    const float* vr   = (const float*)d_in[2];
    const float* Wv   = (const float*)d_in[3];
    const float* bv   = (const float*)d_in[4];
    const float* Woff = (const float*)d_in[5];
    const float* boff = (const float*)d_in[6];
    const float* Wa   = (const float*)d_in[7];
    const float* ba   = (const float*)d_in[8];
    const float* Wo   = (const float*)d_in[9];
    const float* bo   = (const float*)d_in[10];
    const float* g1   = (const float*)d_in[11];
    const float* be1  = (const float*)d_in[12];
    const float* Wl1  = (const float*)d_in[13];
    const float* bl1  = (const float*)d_in[14];
    const float* Wl2  = (const float*)d_in[15];
    const float* bl2  = (const float*)d_in[16];
    const float* g2   = (const float*)d_in[17];
    const float* be2  = (const float*)d_in[18];
    float* out = (float*)d_out;

    float *x, *offaw, *ref, *bq;
    __half *xh, *qh, *valh, *attnh, *ffnh;
    __half *wvh, *wqh, *woh, *wl1h, *wl2h;
    cudaGetSymbolAddress((void**)&x,     g_x);
    cudaGetSymbolAddress((void**)&xh,    g_xh);
    cudaGetSymbolAddress((void**)&qh,    g_qh);
    cudaGetSymbolAddress((void**)&valh,  g_valh);
    cudaGetSymbolAddress((void**)&offaw, g_offaw);
    cudaGetSymbolAddress((void**)&attnh, g_attnh);
    cudaGetSymbolAddress((void**)&ffnh,  g_ffnh);
    cudaGetSymbolAddress((void**)&ref,   g_ref);
    cudaGetSymbolAddress((void**)&wvh,   g_wvh);
    cudaGetSymbolAddress((void**)&wqh,   g_wqh);
    cudaGetSymbolAddress((void**)&woh,   g_woh);
    cudaGetSymbolAddress((void**)&wl1h,  g_wl1h);
    cudaGetSymbolAddress((void**)&wl2h,  g_wl2h);
    cudaGetSymbolAddress((void**)&bq,    g_bq);

    cudaFuncSetAttribute(gemmk,  cudaFuncAttributeMaxDynamicSharedMemorySize, SMEMG);
    cudaFuncSetAttribute(gemmln, cudaFuncAttributeMaxDynamicSharedMemorySize, SMEML);

    pre_kernel<<<NCVT + NINIT + NREF, 256>>>(Wv, Woff, Wa, Wo, Wl1, Wl2, boff, ba,
                                             wvh, wqh, woh, wl1h, wl2h, bq,
                                             src, pos, x, xh, qh, vr, ref);

    dim3 gMerged(DM / TN + NQ / TN, MROWS / TM);   // (5, 85)
    dim3 gFF(DFFN / TN, MROWS / TM);               // (8, 85)
    dim3 gLN(1, MROWS / 32);                       // (1, 340)

    for (int l = 0; l < NLAYERS; l++) {
        GP pv  { xh, wvh + (size_t)l * DM * DM, bv + l * DM, valh, DM, DM, 1 };
        GP pq  { qh, wqh + (size_t)l * NQ * DM, bq + l * NQ, offaw, DM, NQ, 0 };
        gemmk<<<gMerged, 256, SMEMG>>>(pv, pq, DM / TN);

        sample_kernel<<<MROWS, 256>>>(valh, offaw, ref, attnh);

        GLP po { attnh, woh + (size_t)l * DM * DM, bo + l * DM,
                 g1 + l * DM, be1 + l * DM, pos, x, x, xh, qh, DM, 3 };
        gemmln<<<gLN, 256, SMEML>>>(po);

        GP pf1 { xh, wl1h + (size_t)l * DM * DFFN, bl1 + l * DFFN, ffnh, DM, DFFN, 2 };
        gemmk<<<gFF, 256, SMEMG>>>(pf1, pf1, gFF.x);

        bool last = (l == NLAYERS - 1);
        GLP pf2 { ffnh, wl2h + (size_t)l * DFFN * DM, bl2 + l * DM,
                  g2 + l * DM, be2 + l * DM, pos, x,
                  last ? out : x, xh, qh, DFFN, last ? 5 : 4 };
        gemmln<<<gLN, 256, SMEML>>>(pf2);
    }
}

// round 16
// speedup vs baseline: 1.0329x; 1.0071x over previous
#include <cuda_runtime.h>
#include <cuda_fp16.h>
#include <math.h>

#define LEN 5440
#define NBATCH 2
#define MROWS (NBATCH*LEN)   /* 10880 */
#define DM 256
#define NH 8
#define DFFN 1024
#define NLAYERS 2
#define NQ 384

// gemmk tile: 128 x 128, K-chunk 64, 3-stage
#define TM 128
#define TN 128
#define KC 64
#define NSTAGE 3
#define ABYTES 16384
#define BBYTES 16384
#define SMEMG (NSTAGE*(ABYTES+BBYTES))   /* 98304 */

// gemmln tile: 32 x 256, 2-stage
#define LABYTES (32*128)     /* 4096 */
#define LBBYTES (256*128)    /* 32768 */
#define SMEML (2*(LABYTES+LBBYTES))   /* 73728 */

// preamble block ranges
#define NCVT (NLAYERS*737)         /* 1474 */
#define NINIT ((MROWS*DM+255)/256) /* 10880 */
#define NREF  ((MROWS+255)/256)    /* 43 */

__constant__ int c_HW[4] = {64, 32, 16, 8};
__constant__ int c_S[4]  = {0, 4096, 5120, 5376};

// ---------------- scratch ----------------
__device__ __align__(16) float  g_x[MROWS * DM];
__device__ __align__(16) __half g_xh[MROWS * DM];
__device__ __align__(16) __half g_qh[MROWS * DM];
__device__ __align__(16) __half g_valh[MROWS * DM];
__device__ __align__(16) float  g_offaw[MROWS * NQ];
__device__ __align__(16) __half g_attnh[MROWS * DM];
__device__ __align__(16) __half g_ffnh[MROWS * DFFN];
__device__ __align__(16) float  g_ref[MROWS * 8];
__device__ __align__(16) __half g_wvh[NLAYERS * DM * DM];
__device__ __align__(16) __half g_wqh[NLAYERS * NQ * DM];
__device__ __align__(16) __half g_woh[NLAYERS * DM * DM];
__device__ __align__(16) __half g_wl1h[NLAYERS * DM * DFFN];
__device__ __align__(16) __half g_wl2h[NLAYERS * DFFN * DM];
__device__ __align__(16) float  g_bq[NLAYERS * NQ];

// ---------------- helpers ----------------
__device__ __forceinline__ void cpa16(unsigned saddr, const void* g) {
    asm volatile("cp.async.cg.shared.global [%0], [%1], 16;" :: "r"(saddr), "l"(g));
}
__device__ __forceinline__ void ldsm4(unsigned& r0, unsigned& r1, unsigned& r2, unsigned& r3,
                                      unsigned addr) {
    asm volatile("ldmatrix.sync.aligned.m8n8.x4.shared.b16 {%0,%1,%2,%3}, [%4];"
                 : "=r"(r0), "=r"(r1), "=r"(r2), "=r"(r3) : "r"(addr));
}
#define MMA16816(C, A, B0, B1) \
    asm volatile("mma.sync.aligned.m16n8k16.row.col.f32.f16.f16.f32 " \
                 "{%0,%1,%2,%3}, {%4,%5,%6,%7}, {%8,%9}, {%0,%1,%2,%3};\n" \
                 : "+f"((C)[0]), "+f"((C)[1]), "+f"((C)[2]), "+f"((C)[3]) \
                 : "r"((A)[0]), "r"((A)[1]), "r"((A)[2]), "r"((A)[3]), "r"(B0), "r"(B1))

// ---------------- merged preamble: weight cvt+transpose | init | refpts ----------------
__global__ void pre_kernel(
    const float* __restrict__ Wv, const float* __restrict__ Woff, const float* __restrict__ Wa,
    const float* __restrict__ Wo, const float* __restrict__ Wl1, const float* __restrict__ Wl2,
    const float* __restrict__ boff, const float* __restrict__ ba,
    __half* __restrict__ wvh, __half* __restrict__ wqh, __half* __restrict__ woh,
    __half* __restrict__ wl1h, __half* __restrict__ wl2h, float* __restrict__ bq,
    const float* __restrict__ src, const float* __restrict__ pos,
    float* __restrict__ x, __half* __restrict__ xh, __half* __restrict__ qh,
    const float* __restrict__ vr, float* __restrict__ ref)
{
    __shared__ float tile[32][33];
    int b = blockIdx.x;
    int tid = threadIdx.x;

    if (b >= NCVT + NINIT) {                 // ---- refpts ----
        int idx = (b - NCVT - NINIT) * 256 + tid;
        if (idx >= MROWS) return;
        int n = idx / LEN, t = idx % LEN;
        int lvl = 3;
        if (t < 4096) lvl = 0; else if (t < 5120) lvl = 1; else if (t < 5376) lvl = 2;
        int s = c_S[lvl], hw = c_HW[lvl];
        int local = t - s;
        int i = local / hw, j = local % hw;
        float ry = (i + 0.5f) / (vr[(n * 4 + lvl) * 2 + 1] * (float)hw);
        float rx = (j + 0.5f) / (vr[(n * 4 + lvl) * 2 + 0] * (float)hw);
#pragma unroll
        for (int l2 = 0; l2 < 4; l2++) {
            ref[idx * 8 + l2 * 2 + 0] = rx * vr[(n * 4 + l2) * 2 + 0];
            ref[idx * 8 + l2 * 2 + 1] = ry * vr[(n * 4 + l2) * 2 + 1];
        }
        return;
    }
    if (b >= NCVT) {                          // ---- init ----
        int i = (b - NCVT) * 256 + tid;
        float s = src[i];
        x[i] = s;
        xh[i] = __float2half_rn(s);
        qh[i] = __float2half_rn(s + pos[i]);
        return;
    }
    // ---- weight convert + transpose ----
    int l = b / 737, r = b % 737;
    int tx = tid & 31, ty = tid >> 5;
    if (r == 736) {
        for (int i = tid; i < NQ; i += 256)
            bq[l * NQ + i] = (i < 256) ? boff[l * 256 + i] : ba[l * 128 + i - 256];
        return;
    }
    const float* srcw; __half* dst; int K, N, t, rowOff = 0;
    if (r < 64)       { srcw = Wv   + (size_t)l * 256 * 256;  dst = wvh  + (size_t)l * 256 * 256;  K = 256;  N = 256;  t = r; }
    else if (r < 128) { srcw = Woff + (size_t)l * 256 * 256;  dst = wqh  + (size_t)l * NQ * 256;   K = 256;  N = 256;  t = r - 64; }
    else if (r < 160) { srcw = Wa   + (size_t)l * 256 * 128;  dst = wqh  + (size_t)l * NQ * 256;   K = 256;  N = 128;  t = r - 128; rowOff = 256; }
    else if (r < 224) { srcw = Wo   + (size_t)l * 256 * 256;  dst = woh  + (size_t)l * 256 * 256;  K = 256;  N = 256;  t = r - 160; }
    else if (r < 480) { srcw = Wl1  + (size_t)l * 256 * 1024; dst = wl1h + (size_t)l * 256 * 1024; K = 256;  N = 1024; t = r - 224; }
    else              { srcw = Wl2  + (size_t)l * 1024 * 256; dst = wl2h + (size_t)l * 1024 * 256; K = 1024; N = 256;  t = r - 480; }
    int tn = t % (N / 32), tk = t / (N / 32);
    int k0 = tk * 32, n0 = tn * 32;
#pragma unroll
    for (int i = ty; i < 32; i += 8)
        tile[i][tx] = srcw[(size_t)(k0 + i) * N + n0 + tx];
    __syncthreads();
#pragma unroll
    for (int i = ty; i < 32; i += 8)
        dst[(size_t)(rowOff + n0 + i) * K + k0 + tx] = __float2half_rn(tile[tx][i]);
}

// ---------------- gemmk: 128x128 tile, 3-stage ----------------
struct GP {
    const __half* A; const __half* W; const float* bias; void* C;
    int K; int Nc; int mode;
};

__global__ void __launch_bounds__(256, 2) gemmk(GP p0, GP p1, int split)
{
    extern __shared__ char smc[];
    unsigned sbase = (unsigned)__cvta_generic_to_shared(smc);
    unsigned sA = sbase;
    unsigned sB = sbase + NSTAGE * ABYTES;

    GP p; int bx = blockIdx.x;
    if (bx < split) p = p0; else { p = p1; bx -= split; }

    int tid  = threadIdx.x;
    int lane = tid & 31;
    int warp = tid >> 5;
    int wm = warp >> 2, wn = warp & 3;
    int gid = lane >> 2, tq = lane & 3;
    int l7 = lane & 7;

    int rowBase = blockIdx.y * TM;
    int colBase = bx * TN;
    int K = p.K;

    int pr = tid >> 3;
    int pc = tid & 7;
    const __half* Ag = p.A + (size_t)(rowBase + pr) * K + pc * 8;
    const __half* Wg = p.W + (size_t)(colBase + pr) * K + pc * 8;
    unsigned swp = (unsigned)((pc ^ (pr & 7)) << 4);
    unsigned adst0 = sA + (unsigned)(pr * 128) + swp;
    unsigned bdst0 = sB + (unsigned)(pr * 128) + swp;

    auto issue = [&](int s, int k0) {
        unsigned ad = adst0 + (unsigned)(s * ABYTES);
        unsigned bd = bdst0 + (unsigned)(s * BBYTES);
#pragma unroll
        for (int i = 0; i < 4; i++) {
            cpa16(ad + (unsigned)(i * 4096), Ag + (size_t)(32 * i) * K + k0);
            cpa16(bd + (unsigned)(i * 4096), Wg + (size_t)(32 * i) * K + k0);
        }
        asm volatile("cp.async.commit_group;");
    };

    int rlocA = lane & 15, hvA = lane >> 4;
    unsigned rowA[4];
#pragma unroll
    for (int mt = 0; mt < 4; mt++)
        rowA[mt] = sA + (unsigned)((wm * 64 + mt * 16 + rlocA) * 128);
    int nrow = ((lane >> 4) & 1) * 8 + l7;
    int hvB = (lane >> 3) & 1;
    unsigned rowB[2];
#pragma unroll
    for (int pp = 0; pp < 2; pp++)
        rowB[pp] = sB + (unsigned)((wn * 32 + pp * 16 + nrow) * 128);

    float c[4][4][4];
#pragma unroll
    for (int i = 0; i < 4; i++)
#pragma unroll
        for (int j = 0; j < 4; j++)
#pragma unroll
            for (int r = 0; r < 4; r++) c[i][j][r] = 0.f;

    int T = K / KC;
    issue(0, 0);
    issue(1, KC);

#pragma unroll 1
    for (int t = 0; t < T; t++) {
        asm volatile("cp.async.wait_group 1;");
        __syncthreads();
        if (t + 2 < T) issue((t + 2) % NSTAGE, (t + 2) * KC);
        else asm volatile("cp.async.commit_group;");

        unsigned aoff = (unsigned)((t % NSTAGE) * ABYTES);
        unsigned boff = (unsigned)((t % NSTAGE) * BBYTES);

#pragma unroll
        for (int ks = 0; ks < 4; ks++) {
            unsigned swcA = (unsigned)(((2 * ks + hvA) ^ l7) << 4);
            unsigned swcB = (unsigned)(((2 * ks + hvB) ^ l7) << 4);
            unsigned aa[4][4], bb[2][4];
#pragma unroll
            for (int mt = 0; mt < 4; mt++)
                ldsm4(aa[mt][0], aa[mt][1], aa[mt][2], aa[mt][3], rowA[mt] + aoff + swcA);
#pragma unroll
            for (int pp = 0; pp < 2; pp++)
                ldsm4(bb[pp][0], bb[pp][1], bb[pp][2], bb[pp][3], rowB[pp] + boff + swcB);
#pragma unroll
            for (int pp = 0; pp < 2; pp++)
#pragma unroll
                for (int q = 0; q < 2; q++) {
                    int nt = 2 * pp + q;
#pragma unroll
                    for (int mt = 0; mt < 4; mt++)
                        MMA16816(c[mt][nt], aa[mt], bb[pp][2 * q], bb[pp][2 * q + 1]);
                }
        }
        // no trailing sync: next iteration's top sync orders stage reuse
    }

    int Nc = p.Nc, mode = p.mode;
#pragma unroll
    for (int mt = 0; mt < 4; mt++) {
#pragma unroll
        for (int nt = 0; nt < 4; nt++) {
            int r0 = rowBase + wm * 64 + mt * 16 + gid;
            int cc = colBase + wn * 32 + nt * 8 + tq * 2;
            float b0v = p.bias[cc], b1v = p.bias[cc + 1];
            float v0 = c[mt][nt][0] + b0v, v1 = c[mt][nt][1] + b1v;
            float v2 = c[mt][nt][2] + b0v, v3 = c[mt][nt][3] + b1v;
            if (mode == 0) {
                float* C = (float*)p.C;
                *(float2*)(C + (size_t)r0 * Nc + cc)       = make_float2(v0, v1);
                *(float2*)(C + (size_t)(r0 + 8) * Nc + cc) = make_float2(v2, v3);
            } else {
                if (mode == 2) {
                    v0 = fmaxf(v0, 0.f); v1 = fmaxf(v1, 0.f);
                    v2 = fmaxf(v2, 0.f); v3 = fmaxf(v3, 0.f);
                }
                __half* C = (__half*)p.C;
                *(__half2*)(C + (size_t)r0 * Nc + cc)       = __floats2half2_rn(v0, v1);
                *(__half2*)(C + (size_t)(r0 + 8) * Nc + cc) = __floats2half2_rn(v2, v3);
            }
        }
    }
}

// ---------------- gemmln: 32x256 tile, fused bias+residual+LayerNorm ----------------
// mode: 3 = write x + xh ; 4 = write x + xh + qh ; 5 = final, write out only.
struct GLP {
    const __half* A; const __half* W; const float* bias;
    const float* g; const float* be; const float* pos;
    const float* xres; float* xout; __half* xh; __half* qh;
    int K; int mode;
};

__global__ void __launch_bounds__(256, 3) gemmln(GLP p)
{
    extern __shared__ char smc[];
    unsigned sbase = (unsigned)__cvta_generic_to_shared(smc);
    unsigned sA = sbase;
    unsigned sB = sbase + 2 * LABYTES;

    int tid  = threadIdx.x;
    int lane = tid & 31;
    int wn   = tid >> 5;            // warp = 32-col group 0..7
    int gid = lane >> 2, tq = lane & 3;
    int l7 = lane & 7;

    int rowBase = blockIdx.y * 32;
    int K = p.K;

    int pr = tid >> 3;              // 0..31
    int pc = tid & 7;
    const __half* Ag = p.A + (size_t)(rowBase + pr) * K + pc * 8;
    const __half* Wg = p.W + (size_t)pr * K + pc * 8;
    unsigned swp = (unsigned)((pc ^ (pr & 7)) << 4);
    unsigned adst0 = sA + (unsigned)(pr * 128) + swp;
    unsigned bdst0 = sB + (unsigned)(pr * 128) + swp;

    auto issue = [&](int s, int k0) {
        cpa16(adst0 + (unsigned)(s * LABYTES), Ag + k0);
        unsigned bd = bdst0 + (unsigned)(s * LBBYTES);
#pragma unroll
        for (int i = 0; i < 8; i++)
            cpa16(bd + (unsigned)(i * 4096), Wg + (size_t)(32 * i) * K + k0);
        asm volatile("cp.async.commit_group;");
    };

    int rlocA = lane & 15, hvA = lane >> 4;
    unsigned rowA[2];
#pragma unroll
    for (int mt = 0; mt < 2; mt++)
        rowA[mt] = sA + (unsigned)((mt * 16 + rlocA) * 128);
    int nrow = ((lane >> 4) & 1) * 8 + l7;
    int hvB = (lane >> 3) & 1;
    unsigned rowB[2];
#pragma unroll
    for (int pp = 0; pp < 2; pp++)
        rowB[pp] = sB + (unsigned)((wn * 32 + pp * 16 + nrow) * 128);

    float c[2][4][4];
#pragma unroll
    for (int i = 0; i < 2; i++)
#pragma unroll
        for (int j = 0; j < 4; j++)
#pragma unroll
            for (int r = 0; r < 4; r++) c[i][j][r] = 0.f;

    int T = K / KC;
    issue(0, 0);
    issue(1, KC);

#pragma unroll 1
    for (int t = 0; t < T; t++) {
        asm volatile("cp.async.wait_group 1;");
        __syncthreads();

        unsigned aoff = (unsigned)((t & 1) * LABYTES);
        unsigned boff = (unsigned)((t & 1) * LBBYTES);

#pragma unroll
        for (int ks = 0; ks < 4; ks++) {
            unsigned swcA = (unsigned)(((2 * ks + hvA) ^ l7) << 4);
            unsigned swcB = (unsigned)(((2 * ks + hvB) ^ l7) << 4);
            unsigned aa[2][4], bb[2][4];
#pragma unroll
            for (int mt = 0; mt < 2; mt++)
                ldsm4(aa[mt][0], aa[mt][1], aa[mt][2], aa[mt][3], rowA[mt] + aoff + swcA);
#pragma unroll
            for (int pp = 0; pp < 2; pp++)
                ldsm4(bb[pp][0], bb[pp][1], bb[pp][2], bb[pp][3], rowB[pp] + boff + swcB);
#pragma unroll
            for (int pp = 0; pp < 2; pp++)
#pragma unroll
                for (int q = 0; q < 2; q++) {
                    int nt = 2 * pp + q;
#pragma unroll
                    for (int mt = 0; mt < 2; mt++)
                        MMA16816(c[mt][nt], aa[mt], bb[pp][2 * q], bb[pp][2 * q + 1]);
                }
        }
        __syncthreads();   // stage t fully consumed before its buffer is refilled
        if (t + 2 < T) issue(t & 1, (t + 2) * KC);
        else asm volatile("cp.async.commit_group;");
    }

    // ---- fused epilogue: bias + residual, LayerNorm per row ----
    float* red = (float*)smc;   // 32 rows x (sum, sumsq)
    if (tid < 64) red[tid] = 0.f;
    __syncthreads();

#pragma unroll
    for (int mt = 0; mt < 2; mt++) {
        int rl0 = mt * 16 + gid;
        int r0 = rowBase + rl0;
        float s0 = 0.f, ss0 = 0.f, s1 = 0.f, ss1 = 0.f;
#pragma unroll
        for (int nt = 0; nt < 4; nt++) {
            int cc = wn * 32 + nt * 8 + tq * 2;
            float b0 = __ldg(p.bias + cc), b1 = __ldg(p.bias + cc + 1);
            float2 x0 = *(const float2*)(p.xres + (size_t)r0 * DM + cc);
            float2 x1 = *(const float2*)(p.xres + (size_t)(r0 + 8) * DM + cc);
            float v0 = c[mt][nt][0] + b0 + x0.x;
            float v1 = c[mt][nt][1] + b1 + x0.y;
            float v2 = c[mt][nt][2] + b0 + x1.x;
            float v3 = c[mt][nt][3] + b1 + x1.y;
            c[mt][nt][0] = v0; c[mt][nt][1] = v1; c[mt][nt][2] = v2; c[mt][nt][3] = v3;
            s0 += v0 + v1; ss0 += v0 * v0 + v1 * v1;
            s1 += v2 + v3; ss1 += v2 * v2 + v3 * v3;
        }
#pragma unroll
        for (int o = 1; o <= 2; o <<= 1) {
            s0  += __shfl_xor_sync(0xffffffffu, s0, o);
            ss0 += __shfl_xor_sync(0xffffffffu, ss0, o);
            s1  += __shfl_xor_sync(0xffffffffu, s1, o);
            ss1 += __shfl_xor_sync(0xffffffffu, ss1, o);
        }
        if (tq == 0) {
            atomicAdd(&red[2 * rl0], s0);
            atomicAdd(&red[2 * rl0 + 1], ss0);
            atomicAdd(&red[2 * (rl0 + 8)], s1);
            atomicAdd(&red[2 * (rl0 + 8) + 1], ss1);
        }
    }
    __syncthreads();

    int mode = p.mode;
#pragma unroll
    for (int mt = 0; mt < 2; mt++) {
        int rl0 = mt * 16 + gid;
        int r0 = rowBase + rl0;
        float mean0 = red[2 * rl0] * (1.0f / DM);
        float var0  = red[2 * rl0 + 1] * (1.0f / DM) - mean0 * mean0;
        float rstd0 = rsqrtf(var0 + 1e-5f);
        float mean1 = red[2 * (rl0 + 8)] * (1.0f / DM);
        float var1  = red[2 * (rl0 + 8) + 1] * (1.0f / DM) - mean1 * mean1;
        float rstd1 = rsqrtf(var1 + 1e-5f);
#pragma unroll
        for (int nt = 0; nt < 4; nt++) {
            int cc = wn * 32 + nt * 8 + tq * 2;
            float gg0 = __ldg(p.g + cc), gg1 = __ldg(p.g + cc + 1);
            float bb0 = __ldg(p.be + cc), bb1 = __ldg(p.be + cc + 1);
            float v0 = (c[mt][nt][0] - mean0) * rstd0 * gg0 + bb0;
            float v1 = (c[mt][nt][1] - mean0) * rstd0 * gg1 + bb1;
            float v2 = (c[mt][nt][2] - mean1) * rstd1 * gg0 + bb0;
            float v3 = (c[mt][nt][3] - mean1) * rstd1 * gg1 + bb1;
            size_t o0 = (size_t)r0 * DM + cc;
            size_t o1 = (size_t)(r0 + 8) * DM + cc;
            if (mode == 5) {
                *(float2*)(p.xout + o0) = make_float2(v0, v1);
                *(float2*)(p.xout + o1) = make_float2(v2, v3);
            } else {
                *(float2*)(p.xout + o0) = make_float2(v0, v1);
                *(float2*)(p.xout + o1) = make_float2(v2, v3);
                *(__half2*)(p.xh + o0) = __floats2half2_rn(v0, v1);
                *(__half2*)(p.xh + o1) = __floats2half2_rn(v2, v3);
                if (mode == 4) {
                    float2 p0 = *(const float2*)(p.pos + o0);
                    float2 p1 = *(const float2*)(p.pos + o1);
                    *(__half2*)(p.qh + o0) = __floats2half2_rn(v0 + p0.x, v1 + p0.y);
                    *(__half2*)(p.qh + o1) = __floats2half2_rn(v2 + p1.x, v3 + p1.y);
                }
            }
        }
    }
}

// ---------------- deformable sampling: dual-point lanes, half2 loads ----------------
__global__ void __launch_bounds__(256) sample_kernel(
    const __half* __restrict__ value, const float* __restrict__ offaw,
    const float* __restrict__ ref, __half* __restrict__ attnh)
{
    int row = blockIdx.x;
    int h = threadIdx.x >> 5;
    int lane = threadIdx.x & 31;
    int grp = lane >> 4;
    int lc  = lane & 15;
    int n = row / LEN;

    float offv = offaw[(size_t)row * NQ + h * 32 + lane];
    float awraw = (lane < 16) ? offaw[(size_t)row * NQ + 256 + h * 16 + lane] : -1e30f;
    float refv = (lane < 8)  ? ref[(size_t)row * 8 + lane] : 0.f;

    float mx = awraw;
#pragma unroll
    for (int o = 8; o; o >>= 1) mx = fmaxf(mx, __shfl_xor_sync(0xffffffffu, mx, o, 16));
    float e = (lane < 16) ? expf(awraw - mx) : 0.f;
    float ssum = e;
#pragma unroll
    for (int o = 8; o; o >>= 1) ssum += __shfl_xor_sync(0xffffffffu, ssum, o, 16);
    float awv = e / ssum;

    const __half* vbase = value + (size_t)n * LEN * 256 + h * 32 + lc * 2;
    float accx = 0.f, accy = 0.f;
#pragma unroll
    for (int i = 0; i < 8; i++) {
        int p = grp * 8 + i;
        int lvl = p >> 2;
        float ox = __shfl_sync(0xffffffffu, offv, 2 * p);
        float oy = __shfl_sync(0xffffffffu, offv, 2 * p + 1);
        float a  = __shfl_sync(0xffffffffu, awv, p);
        float rx = __shfl_sync(0xffffffffu, refv, 2 * lvl);
        float ry = __shfl_sync(0xffffffffu, refv, 2 * lvl + 1);
        int HW = c_HW[lvl], s = c_S[lvl];
        float fw = (float)HW;
        float xf = (rx + ox / fw) * fw - 0.5f;
        float yf = (ry + oy / fw) * fw - 0.5f;
        float x0f = floorf(xf), y0f = floorf(yf);
        int ix = (int)x0f, iy = (int)y0f;
        float wx1 = xf - x0f, wy1 = yf - y0f;
        float wx0 = 1.f - wx1, wy0 = 1.f - wy1;
        const __half* vb = vbase + (size_t)s * 256;
        bool xin0 = (ix >= 0) && (ix < HW);
        bool xin1 = (ix + 1 >= 0) && (ix + 1 < HW);
        bool yin0 = (iy >= 0) && (iy < HW);
        bool yin1 = (iy + 1 >= 0) && (iy + 1 < HW);
        float sx = 0.f, sy = 0.f;
        if (xin0 && yin0) {
            float2 v = __half22float2(*(const __half2*)(vb + (size_t)(iy * HW + ix) * 256));
            float w = wx0 * wy0; sx += w * v.x; sy += w * v.y;
        }
        if (xin1 && yin0) {
            float2 v = __half22float2(*(const __half2*)(vb + (size_t)(iy * HW + ix + 1) * 256));
            float w = wx1 * wy0; sx += w * v.x; sy += w * v.y;
        }
        if (xin0 && yin1) {
            float2 v = __half22float2(*(const __half2*)(vb + (size_t)((iy + 1) * HW + ix) * 256));
            float w = wx0 * wy1; sx += w * v.x; sy += w * v.y;
        }
        if (xin1 && yin1) {
            float2 v = __half22float2(*(const __half2*)(vb + (size_t)((iy + 1) * HW + ix + 1) * 256));
            float w = wx1 * wy1; sx += w * v.x; sy += w * v.y;
        }
        accx += a * sx;
        accy += a * sy;
    }
    accx += __shfl_down_sync(0xffffffffu, accx, 16);
    accy += __shfl_down_sync(0xffffffffu, accy, 16);
    if (lane < 16)
        *(__half2*)(attnh + (size_t)row * 256 + h * 32 + lc * 2) = __floats2half2_rn(accx, accy);
}

// ---------------- launch ----------------
extern "C" void kernel_launch(void* const* d_in, const int* in_sizes, int n_in,
                              void* d_out, int out_size)
{
    (void)in_sizes; (void)n_in; (void)out_size;
    const float* src  = (const float*)d_in[0];
    const float* pos  = (const float*)d_in[1];
    const float* vr   = (const float*)d_in[2];
    const float* Wv   = (const float*)d_in[3];
    const float* bv   = (const float*)d_in[4];
    const float* Woff = (const float*)d_in[5];
    const float* boff = (const float*)d_in[6];
    const float* Wa   = (const float*)d_in[7];
    const float* ba   = (const float*)d_in[8];
    const float* Wo   = (const float*)d_in[9];
    const float* bo   = (const float*)d_in[10];
    const float* g1   = (const float*)d_in[11];
    const float* be1  = (const float*)d_in[12];
    const float* Wl1  = (const float*)d_in[13];
    const float* bl1  = (const float*)d_in[14];
    const float* Wl2  = (const float*)d_in[15];
    const float* bl2  = (const float*)d_in[16];
    const float* g2   = (const float*)d_in[17];
    const float* be2  = (const float*)d_in[18];
    float* out = (float*)d_out;

    float *x, *offaw, *ref, *bq;
    __half *xh, *qh, *valh, *attnh, *ffnh;
    __half *wvh, *wqh, *woh, *wl1h, *wl2h;
    cudaGetSymbolAddress((void**)&x,     g_x);
    cudaGetSymbolAddress((void**)&xh,    g_xh);
    cudaGetSymbolAddress((void**)&qh,    g_qh);
    cudaGetSymbolAddress((void**)&valh,  g_valh);
    cudaGetSymbolAddress((void**)&offaw, g_offaw);
    cudaGetSymbolAddress((void**)&attnh, g_attnh);
    cudaGetSymbolAddress((void**)&ffnh,  g_ffnh);
    cudaGetSymbolAddress((void**)&ref,   g_ref);
    cudaGetSymbolAddress((void**)&wvh,   g_wvh);
    cudaGetSymbolAddress((void**)&wqh,   g_wqh);
    cudaGetSymbolAddress((void**)&woh,   g_woh);
    cudaGetSymbolAddress((void**)&wl1h,  g_wl1h);
    cudaGetSymbolAddress((void**)&wl2h,  g_wl2h);
    cudaGetSymbolAddress((void**)&bq,    g_bq);

    cudaFuncSetAttribute(gemmk,  cudaFuncAttributeMaxDynamicSharedMemorySize, SMEMG);
    cudaFuncSetAttribute(gemmln, cudaFuncAttributeMaxDynamicSharedMemorySize, SMEML);

    pre_kernel<<<NCVT + NINIT + NREF, 256>>>(Wv, Woff, Wa, Wo, Wl1, Wl2, boff, ba,
                                             wvh, wqh, woh, wl1h, wl2h, bq,
                                             src, pos, x, xh, qh, vr, ref);

    dim3 gMerged(DM / TN + NQ / TN, MROWS / TM);   // (5, 85)
    dim3 gFF(DFFN / TN, MROWS / TM);               // (8, 85)
    dim3 gLN(1, MROWS / 32);                       // (1, 340)

    for (int l = 0; l < NLAYERS; l++) {
        GP pv  { xh, wvh + (size_t)l * DM * DM, bv + l * DM, valh, DM, DM, 1 };
        GP pq  { qh, wqh + (size_t)l * NQ * DM, bq + l * NQ, offaw, DM, NQ, 0 };
        gemmk<<<gMerged, 256, SMEMG>>>(pv, pq, DM / TN);

        sample_kernel<<<MROWS, 256>>>(valh, offaw, ref, attnh);

        GLP po { attnh, woh + (size_t)l * DM * DM, bo + l * DM,
                 g1 + l * DM, be1 + l * DM, pos, x, x, xh, qh, DM, 3 };
        gemmln<<<gLN, 256, SMEML>>>(po);

        GP pf1 { xh, wl1h + (size_t)l * DM * DFFN, bl1 + l * DFFN, ffnh, DM, DFFN, 2 };
        gemmk<<<gFF, 256, SMEMG>>>(pf1, pf1, gFF.x);

        bool last = (l == NLAYERS - 1);
        GLP pf2 { ffnh, wl2h + (size_t)l * DFFN * DM, bl2 + l * DM,
                  g2 + l * DM, be2 + l * DM, pos, x,
                  last ? out : x, xh, qh, DFFN, last ? 5 : 4 };
        gemmln<<<gLN, 256, SMEML>>>(pf2);
    }
}